// round 8
// baseline (speedup 1.0000x reference)
#include <cuda_runtime.h>

#define CLASSES 21
#define TPB 128           // threads per block
#define ILP 2             // anchors per thread
#define APB (ILP * TPB)   // anchors per block = 256
#define TMAXS 256         // max targets held in SMEM (actual T = 200)
#define MAXBLK 2048       // max grid size for partial arrays

// ---------------- per-block partials + completion ticket ---------------------
__device__ double   g_part_cls[MAXBLK];
__device__ double   g_part_reg[MAXBLK];
__device__ int      g_part_pos[MAXBLK];
__device__ unsigned g_ticket;   // zero-initialized; reset by finalizing block

// smooth L1
__device__ __forceinline__ float sl1(float d) {
    float ad = fabsf(d);
    return (ad < 1.0f) ? 0.5f * ad * ad : ad - 0.5f;
}

// Per-anchor tail: focal loss over 21 classes + regression if positive.
__device__ __forceinline__ void anchor_tail(
    int a, bool pos, int bt,
    const float* __restrict__ cls,
    const float4* __restrict__ box,
    float4 an,
    const float4* s_tb, const int* s_tl,
    float& cls_acc, float& reg_acc, int& pos_acc)
{
    int lbl = pos ? s_tl[bt] : 0;   // background one-hot hits class 0

    const float* cp = cls + (long long)a * CLASSES;

    // Branchless negative-form focal for all classes; remember x at the label.
    float fsum = 0.0f;
    float xl = 0.0f;
#pragma unroll
    for (int c = 0; c < CLASSES; c++) {
        float x = __ldg(cp + c);
        if (c == lbl) xl = x;
        float ax = fabsf(x);
        float e  = __expf(-ax);            // exp(-|x|)
        float dd = 1.0f + e;
        float r  = __fdividef(1.0f, dd);   // 1/(1+e)
        float p  = (x >= 0.0f) ? r : e * r;         // sigmoid(x), stable
        float spx = fmaxf(x, 0.0f) + __logf(dd);    // softplus(x), stable
        fsum += p * p * spx;               // neg core: p^2 * (-log_sigmoid(-x))
    }
    // Correct the single target=1 class: remove its neg term, add pos term.
    {
        float ax = fabsf(xl);
        float e  = __expf(-ax);
        float dd = 1.0f + e;
        float r  = __fdividef(1.0f, dd);
        float p  = (xl >= 0.0f) ? r : e * r;
        float pm = (xl >= 0.0f) ? e * r : r;        // 1 - p, stable
        float spx  = fmaxf(xl, 0.0f) + __logf(dd);  // softplus(x)
        float spnx = spx - xl;                      // softplus(-x)
        fsum = 0.75f * (fsum - p * p * spx) + 0.25f * pm * pm * spnx;
    }
    cls_acc += fsum;

    if (pos) {
        float4 bp  = box[a];
        float4 tbv = s_tb[bt];
        float acx = 0.5f * (an.x + an.z), acy = 0.5f * (an.y + an.w);
        float aw  = an.z - an.x,          ah  = an.w - an.y;
        float iaw = __fdividef(1.0f, aw), iah = __fdividef(1.0f, ah);

        float pcx = 0.5f * (bp.x + bp.z), pcy = 0.5f * (bp.y + bp.w);
        float pw  = bp.z - bp.x,          ph  = bp.w - bp.y;
        float tcx = 0.5f * (tbv.x + tbv.z), tcy = 0.5f * (tbv.y + tbv.w);
        float tw  = tbv.z - tbv.x,          th  = tbv.w - tbv.y;

        float d0 = (pcx - acx) * iaw - (tcx - acx) * iaw;
        float d1 = (pcy - acy) * iah - (tcy - acy) * iah;
        float d2 = __logf(pw * iaw) - __logf(tw * iaw);
        float d3 = __logf(ph * iah) - __logf(th * iah);

        reg_acc += sl1(d0) + sl1(d1) + sl1(d2) + sl1(d3);
        pos_acc += 1;
    }
}

__global__ __launch_bounds__(TPB) void rn_loss(
    const float*  __restrict__ cls,
    const float4* __restrict__ box,
    const float4* __restrict__ anc,
    const float4* __restrict__ tb,
    const int*    __restrict__ tl,
    float* __restrict__ out, int nout,
    int A, int T)
{
    __shared__ float4 s_tb[TMAXS];
    __shared__ float  s_area[TMAXS];
    __shared__ int    s_tl[TMAXS];
    __shared__ float  s_wc[TPB / 32];
    __shared__ float  s_wr[TPB / 32];
    __shared__ int    s_wp[TPB / 32];
    __shared__ double s_dc[TPB / 32];
    __shared__ double s_dr[TPB / 32];
    __shared__ int    s_dp[TPB / 32];
    __shared__ bool   s_last;

    const int tid  = threadIdx.x;
    const int lane = tid & 31;
    const int wrp  = tid >> 5;

    for (int t = tid; t < T; t += TPB) {
        float4 b  = tb[t];
        s_tb[t]   = b;
        s_area[t] = (b.z - b.x) * (b.w - b.y);
        s_tl[t]   = tl[t];
    }
    __syncthreads();

    // ---- per-thread anchors (ILP=2) ----
    int      aid[ILP];
    bool     val[ILP];
    float4   an[ILP];
    float    areaB[ILP];
    unsigned best[ILP];
#pragma unroll
    for (int k = 0; k < ILP; k++) {
        aid[k]   = blockIdx.x * APB + k * TPB + tid;
        val[k]   = aid[k] < A;
        an[k]    = val[k] ? anc[aid[k]] : make_float4(2.f, 2.f, 2.001f, 2.001f);
        areaB[k] = (an[k].z - an[k].x) * (an[k].w - an[k].y);
        best[k]  = 0u;
    }

    // ---- IoU argmax: key = floor(iou * 2^23) << 8 | t, single umax chain ----
#pragma unroll 4
    for (int t = 0; t < T; t++) {
        float4 b  = s_tb[t];
        float  aA = s_area[t];
#pragma unroll
        for (int k = 0; k < ILP; k++) {
            float lx = fmaxf(b.x, an[k].x), ly = fmaxf(b.y, an[k].y);
            float rx = fminf(b.z, an[k].z), ry = fminf(b.w, an[k].w);
            float w  = fmaxf(rx - lx, 0.f), h = fmaxf(ry - ly, 0.f);
            float inter = w * h;
            float uni   = (aA + areaB[k]) - inter;       // > 1e-4 for valid boxes
            float iou23 = __fdividef(inter * 8388608.f, uni);  // iou * 2^23
            unsigned iq  = __float2uint_rz(iou23);
            unsigned key = iq * 256u + (unsigned)t;
            best[k] = umax(best[k], key);
        }
    }

    // ---- focal + regression ----
    float cls_acc = 0.f, reg_acc = 0.f;
    int   pos_acc = 0;
#pragma unroll
    for (int k = 0; k < ILP; k++) {
        if (val[k]) {
            int  bt  = (int)(best[k] & 255u);
            bool pos = (best[k] >> 8) >= (1u << 22);   // iou >= 0.5 exactly
            anchor_tail(aid[k], pos, bt, cls, box, an[k], s_tb, s_tl,
                        cls_acc, reg_acc, pos_acc);
        }
    }

    // ---- block reduction: warp shuffle then cross-warp ----
#pragma unroll
    for (int s = 16; s > 0; s >>= 1) {
        cls_acc += __shfl_down_sync(0xffffffffu, cls_acc, s);
        reg_acc += __shfl_down_sync(0xffffffffu, reg_acc, s);
        pos_acc += __shfl_down_sync(0xffffffffu, pos_acc, s);
    }
    if (lane == 0) { s_wc[wrp] = cls_acc; s_wr[wrp] = reg_acc; s_wp[wrp] = pos_acc; }
    __syncthreads();

    if (tid == 0) {
        double c = 0.0, r = 0.0; int p = 0;
#pragma unroll
        for (int w = 0; w < TPB / 32; w++) { c += (double)s_wc[w]; r += (double)s_wr[w]; p += s_wp[w]; }
        g_part_cls[blockIdx.x] = c;
        g_part_reg[blockIdx.x] = r;
        g_part_pos[blockIdx.x] = p;
        __threadfence();
        unsigned tk = atomicAdd(&g_ticket, 1u);
        s_last = (tk == gridDim.x - 1);
    }
    __syncthreads();

    // ---- last block finalizes ----
    if (s_last) {
        __threadfence();
        double c = 0.0, r = 0.0; int p = 0;
        for (int i = tid; i < (int)gridDim.x; i += TPB) {
            c += g_part_cls[i];
            r += g_part_reg[i];
            p += g_part_pos[i];
        }
#pragma unroll
        for (int s = 16; s > 0; s >>= 1) {
            c += __shfl_down_sync(0xffffffffu, c, s);
            r += __shfl_down_sync(0xffffffffu, r, s);
            p += __shfl_down_sync(0xffffffffu, p, s);
        }
        if (lane == 0) { s_dc[wrp] = c; s_dr[wrp] = r; s_dp[wrp] = p; }
        __syncthreads();
        if (tid == 0) {
            double cc = 0.0, rr = 0.0; int pp = 0;
#pragma unroll
            for (int w = 0; w < TPB / 32; w++) { cc += s_dc[w]; rr += s_dr[w]; pp += s_dp[w]; }
            double norm = (pp < 1) ? 1.0 : (double)pp;
            float wc = (float)(cc / norm);
            float wr = (pp > 0) ? (float)(rr / (norm * 4.0)) : 0.0f;
            if (nout > 0) out[0] = wc + wr;
            if (nout > 1) out[1] = wc;
            if (nout > 2) out[2] = wr;
            g_ticket = 0;   // reset for next (graph-replayed) call
        }
    }
}

extern "C" void kernel_launch(void* const* d_in, const int* in_sizes, int n_in,
                              void* d_out, int out_size) {
    const float*  cls = (const float*)d_in[0];
    const float4* box = (const float4*)d_in[1];
    const float4* anc = (const float4*)d_in[2];
    const float4* tb  = (const float4*)d_in[3];
    const int*    tl  = (const int*)d_in[4];

    int A = in_sizes[0] / CLASSES;   // flattened anchor count
    int T = in_sizes[4];             // flattened target count
    if (T > TMAXS) T = TMAXS;

    int grid = (A + APB - 1) / APB;  // A=196608 -> 768
    if (grid > MAXBLK) grid = MAXBLK;

    rn_loss<<<grid, TPB>>>(cls, box, anc, tb, tl,
                           (float*)d_out, out_size, A, T);
}

// round 9
// speedup vs baseline: 1.1923x; 1.1923x over previous
#include <cuda_runtime.h>

#define CLASSES 21
#define TPB 128           // threads per block, 1 anchor per thread
#define TMAXS 256         // max targets held in SMEM (actual T = 200)
#define MAXBLK 2048       // max grid size for partial arrays

// ---------------- per-block partials + completion ticket ---------------------
__device__ double   g_part_cls[MAXBLK];
__device__ double   g_part_reg[MAXBLK];
__device__ int      g_part_pos[MAXBLK];
__device__ unsigned g_ticket;   // zero-initialized; reset by finalizing block

// smooth L1
__device__ __forceinline__ float sl1(float d) {
    float ad = fabsf(d);
    return (ad < 1.0f) ? 0.5f * ad * ad : ad - 0.5f;
}

__global__ __launch_bounds__(TPB, 10) void rn_loss(
    const float*  __restrict__ cls,
    const float4* __restrict__ box,
    const float4* __restrict__ anc,
    const float4* __restrict__ tb,
    const int*    __restrict__ tl,
    float* __restrict__ out, int nout,
    int A, int T)
{
    __shared__ float4 s_tb[TMAXS];
    __shared__ float  s_area[TMAXS];
    __shared__ int    s_tl[TMAXS];
    __shared__ float  s_wc[TPB / 32];
    __shared__ float  s_wr[TPB / 32];
    __shared__ int    s_wp[TPB / 32];
    __shared__ double s_dc[TPB / 32];
    __shared__ double s_dr[TPB / 32];
    __shared__ int    s_dp[TPB / 32];
    __shared__ bool   s_last;

    const int tid  = threadIdx.x;
    const int lane = tid & 31;
    const int wrp  = tid >> 5;

    for (int t = tid; t < T; t += TPB) {
        float4 b  = tb[t];
        s_tb[t]   = b;
        s_area[t] = (b.z - b.x) * (b.w - b.y);
        s_tl[t]   = tl[t];
    }
    __syncthreads();

    // ---- one anchor per thread ----
    const int  a     = blockIdx.x * TPB + tid;
    const bool valid = a < A;
    float4 an    = valid ? anc[a] : make_float4(2.f, 2.f, 2.001f, 2.001f);
    float  areaB = (an.z - an.x) * (an.w - an.y);

    // ---- IoU argmax via g = inter/S (monotone in IoU), 23-bit quantized key.
    // iq = floor(inter * 3*2^22 / S);  iou >= 0.5  <=>  g >= 1/3  <=>  iq >= 2^22
    unsigned best = 0u;
#pragma unroll 8
    for (int t = 0; t < T; t++) {
        float4 b  = s_tb[t];
        float  aA = s_area[t];
        float lx = fmaxf(b.x, an.x), ly = fmaxf(b.y, an.y);
        float rx = fminf(b.z, an.z), ry = fminf(b.w, an.w);
        float w  = fmaxf(rx - lx, 0.f), h = fmaxf(ry - ly, 0.f);
        float inter = w * h;
        float S  = aA + areaB;                       // area_t + area_a (>0)
        float gq = __fdividef(inter * 12582912.f, S);  // g * 3 * 2^22
        unsigned iq  = __float2uint_rz(gq);
        best = umax(best, iq * 256u + (unsigned)t);
    }

    // ---- focal + regression for this anchor ----
    float cls_acc = 0.f, reg_acc = 0.f;
    int   pos_acc = 0;
    if (valid) {
        const int  bt  = (int)(best & 255u);
        const bool pos = (best >> 8) >= (1u << 22);
        const int  lbl = pos ? s_tl[bt] : 0;   // background -> class 0

        const float* cp = cls + (long long)a * CLASSES;

        // Branchless negative-form focal for all classes; remember x at label.
        float fsum = 0.0f;
        float xl = 0.0f;
#pragma unroll
        for (int c = 0; c < CLASSES; c++) {
            float x = __ldg(cp + c);
            if (c == lbl) xl = x;
            float ax = fabsf(x);
            float e  = __expf(-ax);            // exp(-|x|)
            float dd = 1.0f + e;
            float r  = __fdividef(1.0f, dd);   // 1/(1+e)
            float p  = (x >= 0.0f) ? r : e * r;         // sigmoid(x), stable
            float spx = fmaxf(x, 0.0f) + __logf(dd);    // softplus(x), stable
            fsum += p * p * spx;               // p^2 * (-log_sigmoid(-x))
        }
        // Correct the single target=1 class.
        {
            float ax = fabsf(xl);
            float e  = __expf(-ax);
            float dd = 1.0f + e;
            float r  = __fdividef(1.0f, dd);
            float p  = (xl >= 0.0f) ? r : e * r;
            float pm = (xl >= 0.0f) ? e * r : r;        // 1 - p, stable
            float spx  = fmaxf(xl, 0.0f) + __logf(dd);  // softplus(x)
            float spnx = spx - xl;                      // softplus(-x)
            fsum = 0.75f * (fsum - p * p * spx) + 0.25f * pm * pm * spnx;
        }
        cls_acc = fsum;

        if (pos) {
            float4 bp  = box[a];
            float4 tbv = s_tb[bt];
            float acx = 0.5f * (an.x + an.z), acy = 0.5f * (an.y + an.w);
            float aw  = an.z - an.x,          ah  = an.w - an.y;
            float iaw = __fdividef(1.0f, aw), iah = __fdividef(1.0f, ah);

            float pcx = 0.5f * (bp.x + bp.z), pcy = 0.5f * (bp.y + bp.w);
            float pw  = bp.z - bp.x,          ph  = bp.w - bp.y;
            float tcx = 0.5f * (tbv.x + tbv.z), tcy = 0.5f * (tbv.y + tbv.w);
            float tw  = tbv.z - tbv.x,          th  = tbv.w - tbv.y;

            float d0 = (pcx - acx) * iaw - (tcx - acx) * iaw;
            float d1 = (pcy - acy) * iah - (tcy - acy) * iah;
            float d2 = __logf(pw * iaw) - __logf(tw * iaw);
            float d3 = __logf(ph * iah) - __logf(th * iah);

            reg_acc = sl1(d0) + sl1(d1) + sl1(d2) + sl1(d3);
            pos_acc = 1;
        }
    }

    // ---- block reduction: warp shuffle then cross-warp ----
#pragma unroll
    for (int s = 16; s > 0; s >>= 1) {
        cls_acc += __shfl_down_sync(0xffffffffu, cls_acc, s);
        reg_acc += __shfl_down_sync(0xffffffffu, reg_acc, s);
        pos_acc += __shfl_down_sync(0xffffffffu, pos_acc, s);
    }
    if (lane == 0) { s_wc[wrp] = cls_acc; s_wr[wrp] = reg_acc; s_wp[wrp] = pos_acc; }
    __syncthreads();

    if (tid == 0) {
        double c = 0.0, r = 0.0; int p = 0;
#pragma unroll
        for (int w = 0; w < TPB / 32; w++) { c += (double)s_wc[w]; r += (double)s_wr[w]; p += s_wp[w]; }
        g_part_cls[blockIdx.x] = c;
        g_part_reg[blockIdx.x] = r;
        g_part_pos[blockIdx.x] = p;
        __threadfence();
        unsigned tk = atomicAdd(&g_ticket, 1u);
        s_last = (tk == gridDim.x - 1);
    }
    __syncthreads();

    // ---- last block finalizes ----
    if (s_last) {
        __threadfence();
        double c = 0.0, r = 0.0; int p = 0;
        for (int i = tid; i < (int)gridDim.x; i += TPB) {
            c += g_part_cls[i];
            r += g_part_reg[i];
            p += g_part_pos[i];
        }
#pragma unroll
        for (int s = 16; s > 0; s >>= 1) {
            c += __shfl_down_sync(0xffffffffu, c, s);
            r += __shfl_down_sync(0xffffffffu, r, s);
            p += __shfl_down_sync(0xffffffffu, p, s);
        }
        if (lane == 0) { s_dc[wrp] = c; s_dr[wrp] = r; s_dp[wrp] = p; }
        __syncthreads();
        if (tid == 0) {
            double cc = 0.0, rr = 0.0; int pp = 0;
#pragma unroll
            for (int w = 0; w < TPB / 32; w++) { cc += s_dc[w]; rr += s_dr[w]; pp += s_dp[w]; }
            double norm = (pp < 1) ? 1.0 : (double)pp;
            float wc = (float)(cc / norm);
            float wr = (pp > 0) ? (float)(rr / (norm * 4.0)) : 0.0f;
            if (nout > 0) out[0] = wc + wr;
            if (nout > 1) out[1] = wc;
            if (nout > 2) out[2] = wr;
            g_ticket = 0;   // reset for next (graph-replayed) call
        }
    }
}

extern "C" void kernel_launch(void* const* d_in, const int* in_sizes, int n_in,
                              void* d_out, int out_size) {
    const float*  cls = (const float*)d_in[0];
    const float4* box = (const float4*)d_in[1];
    const float4* anc = (const float4*)d_in[2];
    const float4* tb  = (const float4*)d_in[3];
    const int*    tl  = (const int*)d_in[4];

    int A = in_sizes[0] / CLASSES;   // flattened anchor count
    int T = in_sizes[4];             // flattened target count
    if (T > TMAXS) T = TMAXS;

    int grid = (A + TPB - 1) / TPB;  // A=196608 -> 1536
    if (grid > MAXBLK) grid = MAXBLK;

    rn_loss<<<grid, TPB>>>(cls, box, anc, tb, tl,
                           (float*)d_out, out_size, A, T);
}